// round 10
// baseline (speedup 1.0000x reference)
#include <cuda_runtime.h>
#include <cuda_fp16.h>

// Problem constants
#define S_TOTAL    37448       // sum of LAYER_SIZES
#define OUT_TOKENS 5704        // 8 + 64 + 512 + 1024 + 4096
#define BATCH      8
#define TROWS      384         // unified table rows: 256 combo + 64 pos1 + 64 pos2
#define PR_ROWS    8           // rows per projection block (48 chunks)

// Scratch (static device globals; no runtime allocation)
__device__ float  g_Wt3[4 * 256 * 256];        // [kk][e][o]
__device__ float  g_Wt4[8 * 256 * 256];
__device__ __half g_tab3[4 * TROWS * 256];     // [kk][row][o] unified fp16 tables
__device__ __half g_tab4[8 * TROWS * 256];

__device__ __forceinline__ __half2 u2h2(unsigned u) {
    return *reinterpret_cast<const __half2*>(&u);
}

// ---------------------------------------------------------------------------
// Kernel 1: fused tiled transpose for BOTH conv weights.
// blocks [0,32): W3 (K=4, TO=64); blocks [32,96): W4 (K=8, TO=32).
// ---------------------------------------------------------------------------
__global__ void __launch_bounds__(256) transpose_w_all(
    const float* __restrict__ W3, const float* __restrict__ W4)
{
    __shared__ float sm[8448];

    if (blockIdx.x < 32) {
        constexpr int TO = 64, TE = 32, PAD = 65;
        int bid = blockIdx.x;
        int o0 = (bid % 4) * TO;
        int e0 = (bid / 4) * TE;
        const float4* Wv = reinterpret_cast<const float4*>(W3);

        for (int i = threadIdx.x; i < TO * TE; i += 256) {
            int o_l = i / TE, e_l = i % TE;
            float4 v = Wv[(o0 + o_l) * 256 + (e0 + e_l)];
            sm[(0 * TE + e_l) * PAD + o_l] = v.x;
            sm[(1 * TE + e_l) * PAD + o_l] = v.y;
            sm[(2 * TE + e_l) * PAD + o_l] = v.z;
            sm[(3 * TE + e_l) * PAD + o_l] = v.w;
        }
        __syncthreads();
        for (int i = threadIdx.x; i < 4 * TE * TO; i += 256) {
            int kk = i / (TE * TO);
            int rem = i % (TE * TO);
            int e_l = rem / TO, o_l = rem % TO;
            g_Wt3[kk * 65536 + (e0 + e_l) * 256 + (o0 + o_l)] =
                sm[(kk * TE + e_l) * PAD + o_l];
        }
    } else {
        constexpr int TO = 32, TE = 32, PAD = 33;
        int bid = blockIdx.x - 32;
        int o0 = (bid % 8) * TO;
        int e0 = (bid / 8) * TE;
        const float4* Wv = reinterpret_cast<const float4*>(W4);

        for (int i = threadIdx.x; i < TO * TE; i += 256) {
            int o_l = i / TE, e_l = i % TE;
            int idx = (o0 + o_l) * 256 + (e0 + e_l);
#pragma unroll
            for (int q = 0; q < 2; q++) {
                float4 v = Wv[idx * 2 + q];
                sm[((q * 4 + 0) * TE + e_l) * PAD + o_l] = v.x;
                sm[((q * 4 + 1) * TE + e_l) * PAD + o_l] = v.y;
                sm[((q * 4 + 2) * TE + e_l) * PAD + o_l] = v.z;
                sm[((q * 4 + 3) * TE + e_l) * PAD + o_l] = v.w;
            }
        }
        __syncthreads();
        for (int i = threadIdx.x; i < 8 * TE * TO; i += 256) {
            int kk = i / (TE * TO);
            int rem = i % (TE * TO);
            int e_l = rem / TO, o_l = rem % TO;
            g_Wt4[kk * 65536 + (e0 + e_l) * 256 + (o0 + o_l)] =
                sm[(kk * TE + e_l) * PAD + o_l];
        }
    }
}

// ---------------------------------------------------------------------------
// Kernel 2: fused projection; emits unified 384-row fp16 tables per kk-slice.
// Row rr < 256:        (val_emb[rr>>6] + pos0[rr&63]) . W_kk
// 256 <= rr < 320:      pos1[rr-256] . W_kk
// 320 <= rr < 384:      pos2[rr-320] . W_kk
// grid = (48 chunks, 12 slices); block 256 = 64 o-quads x 4 e-quarters.
// ---------------------------------------------------------------------------
__global__ void __launch_bounds__(256) project_all_kernel(
    const float* __restrict__ val3, const float* __restrict__ pos3,
    const float* __restrict__ val4, const float* __restrict__ pos4)
{
    int s  = blockIdx.y;            // slice 0..11 (0-3 -> layer3, 4-11 -> layer4)
    int r0 = blockIdx.x * PR_ROWS;

    const float* Wt; __half* tab; const float* ve; const float* pe;
    if (s < 4) { Wt = g_Wt3 + s * 65536;        tab = g_tab3 + s * (TROWS * 256);
                 ve = val3; pe = pos3; }
    else       { int kk = s - 4;
                 Wt = g_Wt4 + kk * 65536;       tab = g_tab4 + kk * (TROWS * 256);
                 ve = val4; pe = pos4; }

    int o4 = threadIdx.x & 63;
    int eh = threadIdx.x >> 6;
    int ebase = eh * 64;

    __shared__ float  srow[PR_ROWS][256];
    __shared__ float4 sred[3][PR_ROWS][64];

    // Stage 8 (possibly combined) embedding rows
    for (int i = threadIdx.x; i < PR_ROWS * 256; i += 256) {
        int r = i >> 8, c = i & 255;
        int rr = r0 + r;
        float x;
        if (rr < 256) {
            int v  = rr >> 6;
            int q0 = rr & 63;
            x = ve[v * 256 + c] + pe[q0 * 256 + c];
        } else if (rr < 320) {
            x = pe[(64 + (rr - 256)) * 256 + c];
        } else {
            x = pe[(128 + (rr - 320)) * 256 + c];
        }
        srow[r][c] = x;
    }
    __syncthreads();

    float4 acc[PR_ROWS];
#pragma unroll
    for (int r = 0; r < PR_ROWS; r++) acc[r] = make_float4(0.f, 0.f, 0.f, 0.f);

    const float4* Wv = reinterpret_cast<const float4*>(Wt);
#pragma unroll 8
    for (int e = 0; e < 64; e++) {
        float4 w = Wv[(ebase + e) * 64 + o4];
#pragma unroll
        for (int r = 0; r < PR_ROWS; r++) {
            float x = srow[r][ebase + e];
            acc[r].x += x * w.x; acc[r].y += x * w.y;
            acc[r].z += x * w.z; acc[r].w += x * w.w;
        }
    }

    if (eh > 0) {
#pragma unroll
        for (int r = 0; r < PR_ROWS; r++) sred[eh - 1][r][o4] = acc[r];
    }
    __syncthreads();
    if (eh == 0) {
#pragma unroll
        for (int r = 0; r < PR_ROWS; r++) {
            float4 a = acc[r];
            float4 b0 = sred[0][r][o4], b1 = sred[1][r][o4], b2 = sred[2][r][o4];
            a.x += b0.x + b1.x + b2.x;
            a.y += b0.y + b1.y + b2.y;
            a.z += b0.z + b1.z + b2.z;
            a.w += b0.w + b1.w + b2.w;
            __half2* dst = reinterpret_cast<__half2*>(tab + (r0 + r) * 256 + o4 * 4);
            dst[0] = __floats2half2_rn(a.x, a.y);
            dst[1] = __floats2half2_rn(a.z, a.w);
        }
    }
}

// ---------------------------------------------------------------------------
// conv body (shared by conv3-fused and conv4): 3 gathers per kk from the
// unified table. warp = one token.
// ---------------------------------------------------------------------------
template <int K>
__device__ __forceinline__ void conv_body(
    const __half* __restrict__ tab,
    const int* __restrict__ value,
    const int* __restrict__ position,
    const float* __restrict__ bias,
    float* __restrict__ out,
    int gwarp, int lane,
    int in_start, int out_row_start, int t_per_b)
{
    int b = gwarp / t_per_b;
    int t = gwarp % t_per_b;

    int sbase = b * S_TOTAL + in_start + t * K;

    // Lane-parallel raw index fetch (2 coalesced LDGs per warp)
    int vload = (lane < K)     ? value[sbase + lane]        : 0;
    int pload = (lane < 3 * K) ? position[sbase * 3 + lane] : 0;

    // Prefuse (valid for lane < K): combo row + two pos rows.
    int q0l = __shfl_sync(0xffffffffu, pload, (lane * 3)     & 31);
    int q1l = __shfl_sync(0xffffffffu, pload, (lane * 3 + 1) & 31);
    int q2l = __shfl_sync(0xffffffffu, pload, (lane * 3 + 2) & 31);
    int iA = vload * 64 + q0l;       // [0,256)
    int i1 = 256 + q1l;
    int i2 = 320 + q2l;

    float acc[8];
    {
        const float4* bv = reinterpret_cast<const float4*>(bias);
        float4 b0 = bv[lane * 2], b1 = bv[lane * 2 + 1];
        acc[0] = b0.x; acc[1] = b0.y; acc[2] = b0.z; acc[3] = b0.w;
        acc[4] = b1.x; acc[5] = b1.y; acc[6] = b1.z; acc[7] = b1.w;
    }

#pragma unroll
    for (int kk = 0; kk < K; kk++) {
        int rA = __shfl_sync(0xffffffffu, iA, kk);
        int r1 = __shfl_sync(0xffffffffu, i1, kk);
        int r2 = __shfl_sync(0xffffffffu, i2, kk);

        const uint4* P = reinterpret_cast<const uint4*>(tab + kk * (TROWS * 256));
        uint4 ua = P[rA * 32 + lane];
        uint4 u1 = P[r1 * 32 + lane];
        uint4 u2 = P[r2 * 32 + lane];

        __half2 sx = __hadd2(__hadd2(u2h2(ua.x), u2h2(u1.x)), u2h2(u2.x));
        __half2 sy = __hadd2(__hadd2(u2h2(ua.y), u2h2(u1.y)), u2h2(u2.y));
        __half2 sz = __hadd2(__hadd2(u2h2(ua.z), u2h2(u1.z)), u2h2(u2.z));
        __half2 sw = __hadd2(__hadd2(u2h2(ua.w), u2h2(u1.w)), u2h2(u2.w));

        float2 f;
        f = __half22float2(sx); acc[0] += f.x; acc[1] += f.y;
        f = __half22float2(sy); acc[2] += f.x; acc[3] += f.y;
        f = __half22float2(sz); acc[4] += f.x; acc[5] += f.y;
        f = __half22float2(sw); acc[6] += f.x; acc[7] += f.y;
    }

    int row = b * OUT_TOKENS + out_row_start + t;
    float4* dst = reinterpret_cast<float4*>(out + row * 256 + lane * 8);
    dst[0] = make_float4(acc[0], acc[1], acc[2], acc[3]);
    dst[1] = make_float4(acc[4], acc[5], acc[6], acc[7]);
}

// ---------------------------------------------------------------------------
// Kernel 3: conv3 + embed_small fused (block-range branch).
// blocks [0,1024): conv3 token-warps; blocks [1024,2192): embed layers 0-2.
// ---------------------------------------------------------------------------
#define C3_BLOCKS 1024
#define EM_BLOCKS 1168

__global__ void __launch_bounds__(256) conv3_embed_kernel(
    const int* __restrict__ value,
    const int* __restrict__ depth,
    const int* __restrict__ position,
    const float* __restrict__ bias3,
    const float* __restrict__ v0, const float* __restrict__ v1, const float* __restrict__ v2,
    const float* __restrict__ p0, const float* __restrict__ p1, const float* __restrict__ p2,
    const float* __restrict__ d0, const float* __restrict__ d1, const float* __restrict__ d2,
    float* __restrict__ out)
{
    if (blockIdx.x < C3_BLOCKS) {
        int gwarp = (blockIdx.x * 256 + threadIdx.x) >> 5;
        int lane  = threadIdx.x & 31;
        if (gwarp < BATCH * 1024) {
            conv_body<4>(g_tab3, value, position, bias3, out,
                         gwarp, lane, /*in_start=*/584,
                         /*out_row_start=*/584, /*t_per_b=*/1024);
        }
        return;
    }

    // embed path
    int idx = (blockIdx.x - C3_BLOCKS) * 256 + threadIdx.x;
    int lane  = idx & 63;
    int token = idx >> 6;
    if (token >= BATCH * 584) return;
    int b = token / 584;
    int s = token % 584;

    const float *ve, *pe, *de;
    if (s < 8)       { ve = v0; pe = p0; de = d0; }
    else if (s < 72) { ve = v1; pe = p1; de = d1; }
    else             { ve = v2; pe = p2; de = d2; }

    int base = b * S_TOTAL + s;
    int v = value[base];
    int d = depth[base];
    const int* pp = position + base * 3;
    int q0 = pp[0], q1 = pp[1], q2 = pp[2];

    const float4* V  = reinterpret_cast<const float4*>(ve) + v * 64 + lane;
    const float4* P0 = reinterpret_cast<const float4*>(pe) + (q0)       * 64 + lane;
    const float4* P1 = reinterpret_cast<const float4*>(pe) + (64 + q1)  * 64 + lane;
    const float4* P2 = reinterpret_cast<const float4*>(pe) + (128 + q2) * 64 + lane;
    const float4* D  = reinterpret_cast<const float4*>(de) + d * 64 + lane;

    float4 a = *V, x;
    x = *P0; a.x += x.x; a.y += x.y; a.z += x.z; a.w += x.w;
    x = *P1; a.x += x.x; a.y += x.y; a.z += x.z; a.w += x.w;
    x = *P2; a.x += x.x; a.y += x.y; a.z += x.z; a.w += x.w;
    x = *D;  a.x += x.x; a.y += x.y; a.z += x.z; a.w += x.w;

    reinterpret_cast<float4*>(out)[(b * OUT_TOKENS + s) * 64 + lane] = a;
}

// ---------------------------------------------------------------------------
// Kernel 4: conv4 (warp = token, 3 gathers/kk).
// ---------------------------------------------------------------------------
__global__ void __launch_bounds__(256) conv4_kernel(
    const int* __restrict__ value,
    const int* __restrict__ position,
    const float* __restrict__ bias,
    float* __restrict__ out)
{
    int gwarp = (blockIdx.x * 256 + threadIdx.x) >> 5;
    int lane  = threadIdx.x & 31;
    if (gwarp >= BATCH * 4096) return;
    conv_body<8>(g_tab4, value, position, bias, out,
                 gwarp, lane, /*in_start=*/4680,
                 /*out_row_start=*/1608, /*t_per_b=*/4096);
}

// ---------------------------------------------------------------------------
// Launch. Inputs classified BY ELEMENT COUNT (robust to metadata ordering).
// Order: transpose(1), project(2), conv3+embed(3), conv4(4 = ncu slot).
// ---------------------------------------------------------------------------
extern "C" void kernel_launch(void* const* d_in, const int* in_sizes, int n_in,
                              void* d_out, int out_size) {
    const int* value = nullptr;
    const int* depth = nullptr;
    const int* position = nullptr;
    const float* val_emb[5] = {};
    const float* pos_emb[5] = {};
    const float* dep_emb[3] = {};
    const float* conv_w3 = nullptr;
    const float* conv_w4 = nullptr;
    const float* conv_b3 = nullptr;
    const float* conv_b4 = nullptr;

    int n_val = 0, n_pos = 0, n_dep = 0, n_cb = 0, n_vd = 0;
    for (int i = 0; i < n_in; i++) {
        int sz = in_sizes[i];
        const void* p = d_in[i];
        switch (sz) {
            case 299584:
                if (n_vd++ == 0) value = (const int*)p; else depth = (const int*)p;
                break;
            case 898752:  position = (const int*)p; break;
            case 1024:    if (n_val < 5) val_emb[n_val++] = (const float*)p; break;
            case 49152:   if (n_pos < 5) pos_emb[n_pos++] = (const float*)p; break;
            case 1536:    if (n_dep < 3) dep_emb[n_dep++] = (const float*)p; break;
            case 262144:  conv_w3 = (const float*)p; break;
            case 524288:  conv_w4 = (const float*)p; break;
            case 256:
                if (n_cb++ == 0) conv_b3 = (const float*)p; else conv_b4 = (const float*)p;
                break;
            default: break;
        }
    }

    float* out = (float*)d_out;

    // 1: fused transposes
    transpose_w_all<<<96, 256>>>(conv_w3, conv_w4);

    // 2: fused projection -> unified fp16 tables (48 chunks x 12 slices)
    project_all_kernel<<<dim3(TROWS / PR_ROWS, 12), 256>>>(
        val_emb[3], pos_emb[3], val_emb[4], pos_emb[4]);

    // 3: conv3 + embed layers 0-2, one launch
    conv3_embed_kernel<<<C3_BLOCKS + EM_BLOCKS, 256>>>(
        value, depth, position, conv_b3,
        val_emb[0], val_emb[1], val_emb[2],
        pos_emb[0], pos_emb[1], pos_emb[2],
        dep_emb[0], dep_emb[1], dep_emb[2],
        out);

    // 4 (ncu capture slot): conv4 — 32768 token-warps
    conv4_kernel<<<(BATCH * 4096 * 32) / 256, 256>>>(
        value, position, conv_b4, out);
}

// round 11
// speedup vs baseline: 1.1107x; 1.1107x over previous
#include <cuda_runtime.h>
#include <cuda_fp16.h>

// Problem constants
#define S_TOTAL    37448       // sum of LAYER_SIZES
#define OUT_TOKENS 5704        // 8 + 64 + 512 + 1024 + 4096
#define BATCH      8
#define NROWS      196         // 4 val rows + 3*64 pos rows
#define PR_ROWS    4           // rows per projection block (49 chunks)

// Scratch (static device globals; no runtime allocation)
__device__ float  g_Wt3[4 * 256 * 256];          // [kk][e][o]
__device__ float  g_Wt4[8 * 256 * 256];
__device__ __half g_proj3h[4 * NROWS * 256];     // [kk][row][o] fp16 base tables
__device__ __half g_proj4h[8 * NROWS * 256];
__device__ __half g_tabA3[4 * 256 * 256];        // [kk][v*64+q0][o]
__device__ __half g_tabA4[8 * 256 * 256];

__device__ __forceinline__ __half2 u2h2(unsigned u) {
    return *reinterpret_cast<const __half2*>(&u);
}
__device__ __forceinline__ unsigned h22u(__half2 h) {
    return *reinterpret_cast<const unsigned*>(&h);
}

// ---------------------------------------------------------------------------
// Kernel 1: fused tiled transpose for BOTH conv weights.
// ---------------------------------------------------------------------------
__global__ void __launch_bounds__(256) transpose_w_all(
    const float* __restrict__ W3, const float* __restrict__ W4)
{
    __shared__ float sm[8448];

    if (blockIdx.x < 32) {
        constexpr int TO = 64, TE = 32, PAD = 65;
        int bid = blockIdx.x;
        int o0 = (bid % 4) * TO;
        int e0 = (bid / 4) * TE;
        const float4* Wv = reinterpret_cast<const float4*>(W3);

        for (int i = threadIdx.x; i < TO * TE; i += 256) {
            int o_l = i / TE, e_l = i % TE;
            float4 v = Wv[(o0 + o_l) * 256 + (e0 + e_l)];
            sm[(0 * TE + e_l) * PAD + o_l] = v.x;
            sm[(1 * TE + e_l) * PAD + o_l] = v.y;
            sm[(2 * TE + e_l) * PAD + o_l] = v.z;
            sm[(3 * TE + e_l) * PAD + o_l] = v.w;
        }
        __syncthreads();
        for (int i = threadIdx.x; i < 4 * TE * TO; i += 256) {
            int kk = i / (TE * TO);
            int rem = i % (TE * TO);
            int e_l = rem / TO, o_l = rem % TO;
            g_Wt3[kk * 65536 + (e0 + e_l) * 256 + (o0 + o_l)] =
                sm[(kk * TE + e_l) * PAD + o_l];
        }
    } else {
        constexpr int TO = 32, TE = 32, PAD = 33;
        int bid = blockIdx.x - 32;
        int o0 = (bid % 8) * TO;
        int e0 = (bid / 8) * TE;
        const float4* Wv = reinterpret_cast<const float4*>(W4);

        for (int i = threadIdx.x; i < TO * TE; i += 256) {
            int o_l = i / TE, e_l = i % TE;
            int idx = (o0 + o_l) * 256 + (e0 + e_l);
#pragma unroll
            for (int q = 0; q < 2; q++) {
                float4 v = Wv[idx * 2 + q];
                sm[((q * 4 + 0) * TE + e_l) * PAD + o_l] = v.x;
                sm[((q * 4 + 1) * TE + e_l) * PAD + o_l] = v.y;
                sm[((q * 4 + 2) * TE + e_l) * PAD + o_l] = v.z;
                sm[((q * 4 + 3) * TE + e_l) * PAD + o_l] = v.w;
            }
        }
        __syncthreads();
        for (int i = threadIdx.x; i < 8 * TE * TO; i += 256) {
            int kk = i / (TE * TO);
            int rem = i % (TE * TO);
            int e_l = rem / TO, o_l = rem % TO;
            g_Wt4[kk * 65536 + (e0 + e_l) * 256 + (o0 + o_l)] =
                sm[(kk * TE + e_l) * PAD + o_l];
        }
    }
}

// ---------------------------------------------------------------------------
// Kernel 2: fused projection for all 12 kk-slices; emits fp16 base tables.
// ---------------------------------------------------------------------------
__global__ void __launch_bounds__(256) project_all_kernel(
    const float* __restrict__ val3, const float* __restrict__ pos3,
    const float* __restrict__ val4, const float* __restrict__ pos4)
{
    int s  = blockIdx.y;
    int r0 = blockIdx.x * PR_ROWS;

    const float* Wt; __half* proj; const float* ve; const float* pe;
    if (s < 4) { Wt = g_Wt3 + s * 65536;        proj = g_proj3h + s * (NROWS * 256);
                 ve = val3; pe = pos3; }
    else       { int kk = s - 4;
                 Wt = g_Wt4 + kk * 65536;       proj = g_proj4h + kk * (NROWS * 256);
                 ve = val4; pe = pos4; }

    int o4 = threadIdx.x & 63;
    int eh = threadIdx.x >> 6;
    int ebase = eh * 64;

    __shared__ float  srow[PR_ROWS][256];
    __shared__ float4 sred[3][PR_ROWS][64];

    for (int i = threadIdx.x; i < PR_ROWS * 256; i += 256) {
        int r = i >> 8, c = i & 255;
        int rr = r0 + r;
        srow[r][c] = (rr < 4) ? ve[rr * 256 + c] : pe[(rr - 4) * 256 + c];
    }
    __syncthreads();

    float4 acc[PR_ROWS];
#pragma unroll
    for (int r = 0; r < PR_ROWS; r++) acc[r] = make_float4(0.f, 0.f, 0.f, 0.f);

    const float4* Wv = reinterpret_cast<const float4*>(Wt);
#pragma unroll 8
    for (int e = 0; e < 64; e++) {
        float4 w = Wv[(ebase + e) * 64 + o4];
#pragma unroll
        for (int r = 0; r < PR_ROWS; r++) {
            float x = srow[r][ebase + e];
            acc[r].x += x * w.x; acc[r].y += x * w.y;
            acc[r].z += x * w.z; acc[r].w += x * w.w;
        }
    }

    if (eh > 0) {
#pragma unroll
        for (int r = 0; r < PR_ROWS; r++) sred[eh - 1][r][o4] = acc[r];
    }
    __syncthreads();
    if (eh == 0) {
#pragma unroll
        for (int r = 0; r < PR_ROWS; r++) {
            float4 a = acc[r];
            float4 b0 = sred[0][r][o4], b1 = sred[1][r][o4], b2 = sred[2][r][o4];
            a.x += b0.x + b1.x + b2.x;
            a.y += b0.y + b1.y + b2.y;
            a.z += b0.z + b1.z + b2.z;
            a.w += b0.w + b1.w + b2.w;
            __half2* dst = reinterpret_cast<__half2*>(proj + (r0 + r) * 256 + o4 * 4);
            dst[0] = __floats2half2_rn(a.x, a.y);
            dst[1] = __floats2half2_rn(a.z, a.w);
        }
    }
}

// ---------------------------------------------------------------------------
// Kernel 3: build tabA = PV[v] + PP0[q0]   (warp per output row)
// ---------------------------------------------------------------------------
__global__ void __launch_bounds__(256) build_tabA_kernel() {
    int gw   = (blockIdx.x * blockDim.x + threadIdx.x) >> 5;
    int lane = threadIdx.x & 31;
    if (gw >= 12 * 256) return;
    int s   = gw >> 8;
    int row = gw & 255;
    int v   = row >> 6;
    int q0  = row & 63;

    const uint4* proj = reinterpret_cast<const uint4*>(
        (s < 4) ? g_proj3h + s * (NROWS * 256)
                : g_proj4h + (s - 4) * (NROWS * 256));
    uint4* dst = reinterpret_cast<uint4*>(
        (s < 4) ? g_tabA3 + s * (256 * 256)
                : g_tabA4 + (s - 4) * (256 * 256));

    uint4 a = proj[v * 32 + lane];
    uint4 b = proj[(4 + q0) * 32 + lane];
    uint4 r;
    r.x = h22u(__hadd2(u2h2(a.x), u2h2(b.x)));
    r.y = h22u(__hadd2(u2h2(a.y), u2h2(b.y)));
    r.z = h22u(__hadd2(u2h2(a.z), u2h2(b.z)));
    r.w = h22u(__hadd2(u2h2(a.w), u2h2(b.w)));
    dst[row * 32 + lane] = r;
}

// ---------------------------------------------------------------------------
// Kernel C: layers 0-2 (pure embedding sum), fp32 exact.
// ---------------------------------------------------------------------------
__global__ void __launch_bounds__(256) embed_small_kernel(
    const int* __restrict__ value,
    const int* __restrict__ depth,
    const int* __restrict__ position,
    const float* __restrict__ v0, const float* __restrict__ v1, const float* __restrict__ v2,
    const float* __restrict__ p0, const float* __restrict__ p1, const float* __restrict__ p2,
    const float* __restrict__ d0, const float* __restrict__ d1, const float* __restrict__ d2,
    float* __restrict__ out)
{
    int idx = blockIdx.x * blockDim.x + threadIdx.x;
    int lane  = idx & 63;
    int token = idx >> 6;
    if (token >= BATCH * 584) return;
    int b = token / 584;
    int s = token % 584;

    const float *ve, *pe, *de;
    if (s < 8)       { ve = v0; pe = p0; de = d0; }
    else if (s < 72) { ve = v1; pe = p1; de = d1; }
    else             { ve = v2; pe = p2; de = d2; }

    int base = b * S_TOTAL + s;
    int v = value[base];
    int d = depth[base];
    const int* pp = position + base * 3;
    int q0 = pp[0], q1 = pp[1], q2 = pp[2];

    const float4* V  = reinterpret_cast<const float4*>(ve) + v * 64 + lane;
    const float4* P0 = reinterpret_cast<const float4*>(pe) + (q0)       * 64 + lane;
    const float4* P1 = reinterpret_cast<const float4*>(pe) + (64 + q1)  * 64 + lane;
    const float4* P2 = reinterpret_cast<const float4*>(pe) + (128 + q2) * 64 + lane;
    const float4* D  = reinterpret_cast<const float4*>(de) + d * 64 + lane;

    float4 a = *V, x;
    x = *P0; a.x += x.x; a.y += x.y; a.z += x.z; a.w += x.w;
    x = *P1; a.x += x.x; a.y += x.y; a.z += x.z; a.w += x.w;
    x = *P2; a.x += x.x; a.y += x.y; a.z += x.z; a.w += x.w;
    x = *D;  a.x += x.x; a.y += x.y; a.z += x.z; a.w += x.w;

    reinterpret_cast<float4*>(out)[(b * OUT_TOKENS + s) * 64 + lane] = a;
}

// ---------------------------------------------------------------------------
// Kernel D: conv via tabA + proj gathers — 3 gathers per kk,
// SOFTWARE-PIPELINED (double-buffered loads: kk+1's rows load while kk's
// rows are summed). warp = one token.
// ---------------------------------------------------------------------------
template <int K>
__global__ void __launch_bounds__(256) conv_tri_kernel(
    const int* __restrict__ value,
    const int* __restrict__ position,
    const float* __restrict__ bias,
    float* __restrict__ out,
    int in_start, int out_row_start, int t_per_b)
{
    const __half* tabA = (K == 4) ? g_tabA3 : g_tabA4;
    const __half* proj = (K == 4) ? g_proj3h : g_proj4h;

    int gwarp = (blockIdx.x * blockDim.x + threadIdx.x) >> 5;
    int lane  = threadIdx.x & 31;
    if (gwarp >= BATCH * t_per_b) return;
    int b = gwarp / t_per_b;
    int t = gwarp % t_per_b;

    int sbase = b * S_TOTAL + in_start + t * K;

    // Lane-parallel raw index fetch (2 coalesced LDGs per warp)
    int vload = (lane < K)     ? value[sbase + lane]        : 0;
    int pload = (lane < 3 * K) ? position[sbase * 3 + lane] : 0;

    // Prefuse (valid for lane < K): tabA row, and the two proj rows.
    int q0l = __shfl_sync(0xffffffffu, pload, (lane * 3)     & 31);
    int q1l = __shfl_sync(0xffffffffu, pload, (lane * 3 + 1) & 31);
    int q2l = __shfl_sync(0xffffffffu, pload, (lane * 3 + 2) & 31);
    int iA = vload * 64 + q0l;
    int i1 = 68 + q1l;
    int i2 = 132 + q2l;

    float acc[8];
    {
        const float4* bv = reinterpret_cast<const float4*>(bias);
        float4 b0 = bv[lane * 2], b1 = bv[lane * 2 + 1];
        acc[0] = b0.x; acc[1] = b0.y; acc[2] = b0.z; acc[3] = b0.w;
        acc[4] = b1.x; acc[5] = b1.y; acc[6] = b1.z; acc[7] = b1.w;
    }

    // Double-buffered pipeline over kk
    uint4 ua[2], u1[2], u2[2];

    {   // prologue: load kk = 0 into buffer 0
        int rA = __shfl_sync(0xffffffffu, iA, 0);
        int r1 = __shfl_sync(0xffffffffu, i1, 0);
        int r2 = __shfl_sync(0xffffffffu, i2, 0);
        const uint4* PA = reinterpret_cast<const uint4*>(tabA);
        const uint4* PP = reinterpret_cast<const uint4*>(proj);
        ua[0] = PA[rA * 32 + lane];
        u1[0] = PP[r1 * 32 + lane];
        u2[0] = PP[r2 * 32 + lane];
    }

#pragma unroll
    for (int kk = 0; kk < K; kk++) {
        int cur = kk & 1;
        if (kk + 1 < K) {   // issue next iteration's loads before this math
            int nxt = (kk + 1) & 1;
            int rA = __shfl_sync(0xffffffffu, iA, kk + 1);
            int r1 = __shfl_sync(0xffffffffu, i1, kk + 1);
            int r2 = __shfl_sync(0xffffffffu, i2, kk + 1);
            const uint4* PA =
                reinterpret_cast<const uint4*>(tabA + (kk + 1) * (256 * 256));
            const uint4* PP =
                reinterpret_cast<const uint4*>(proj + (kk + 1) * (NROWS * 256));
            ua[nxt] = PA[rA * 32 + lane];
            u1[nxt] = PP[r1 * 32 + lane];
            u2[nxt] = PP[r2 * 32 + lane];
        }

        __half2 sx = __hadd2(__hadd2(u2h2(ua[cur].x), u2h2(u1[cur].x)), u2h2(u2[cur].x));
        __half2 sy = __hadd2(__hadd2(u2h2(ua[cur].y), u2h2(u1[cur].y)), u2h2(u2[cur].y));
        __half2 sz = __hadd2(__hadd2(u2h2(ua[cur].z), u2h2(u1[cur].z)), u2h2(u2[cur].z));
        __half2 sw = __hadd2(__hadd2(u2h2(ua[cur].w), u2h2(u1[cur].w)), u2h2(u2[cur].w));

        float2 f;
        f = __half22float2(sx); acc[0] += f.x; acc[1] += f.y;
        f = __half22float2(sy); acc[2] += f.x; acc[3] += f.y;
        f = __half22float2(sz); acc[4] += f.x; acc[5] += f.y;
        f = __half22float2(sw); acc[6] += f.x; acc[7] += f.y;
    }

    int row = b * OUT_TOKENS + out_row_start + t;
    float4* dst = reinterpret_cast<float4*>(out + row * 256 + lane * 8);
    dst[0] = make_float4(acc[0], acc[1], acc[2], acc[3]);
    dst[1] = make_float4(acc[4], acc[5], acc[6], acc[7]);
}

// ---------------------------------------------------------------------------
// Launch. Inputs classified BY ELEMENT COUNT. Order as R9:
// transpose(1), project(2), buildA(3), conv4(4 = ncu slot), conv3(5), embed(6).
// ---------------------------------------------------------------------------
extern "C" void kernel_launch(void* const* d_in, const int* in_sizes, int n_in,
                              void* d_out, int out_size) {
    const int* value = nullptr;
    const int* depth = nullptr;
    const int* position = nullptr;
    const float* val_emb[5] = {};
    const float* pos_emb[5] = {};
    const float* dep_emb[3] = {};
    const float* conv_w3 = nullptr;
    const float* conv_w4 = nullptr;
    const float* conv_b3 = nullptr;
    const float* conv_b4 = nullptr;

    int n_val = 0, n_pos = 0, n_dep = 0, n_cb = 0, n_vd = 0;
    for (int i = 0; i < n_in; i++) {
        int sz = in_sizes[i];
        const void* p = d_in[i];
        switch (sz) {
            case 299584:
                if (n_vd++ == 0) value = (const int*)p; else depth = (const int*)p;
                break;
            case 898752:  position = (const int*)p; break;
            case 1024:    if (n_val < 5) val_emb[n_val++] = (const float*)p; break;
            case 49152:   if (n_pos < 5) pos_emb[n_pos++] = (const float*)p; break;
            case 1536:    if (n_dep < 3) dep_emb[n_dep++] = (const float*)p; break;
            case 262144:  conv_w3 = (const float*)p; break;
            case 524288:  conv_w4 = (const float*)p; break;
            case 256:
                if (n_cb++ == 0) conv_b3 = (const float*)p; else conv_b4 = (const float*)p;
                break;
            default: break;
        }
    }

    float* out = (float*)d_out;

    // 1: fused transposes
    transpose_w_all<<<96, 256>>>(conv_w3, conv_w4);

    // 2: fused projection -> fp16 base tables
    project_all_kernel<<<dim3(NROWS / PR_ROWS, 12), 256>>>(
        val_emb[3], pos_emb[3], val_emb[4], pos_emb[4]);

    // 3: tabA build
    build_tabA_kernel<<<(12 * 256) / 8, 256>>>();

    // 4 (ncu capture slot): conv4 — 32768 token-warps
    {
        int warps4 = BATCH * 4096;
        conv_tri_kernel<8><<<(warps4 * 32 + 255) / 256, 256>>>(
            value, position, conv_b4, out,
            /*in_start=*/4680, /*out_row_start=*/1608, /*t_per_b=*/4096);
    }

    // 5: conv3 — 8192 token-warps
    {
        int warps3 = BATCH * 1024;
        conv_tri_kernel<4><<<(warps3 * 32 + 255) / 256, 256>>>(
            value, position, conv_b3, out,
            /*in_start=*/584, /*out_row_start=*/584, /*t_per_b=*/1024);
    }

    // 6: small layers 0-2
    {
        int threads = BATCH * 584 * 64;
        embed_small_kernel<<<(threads + 255) / 256, 256>>>(
            value, depth, position,
            val_emb[0], val_emb[1], val_emb[2],
            pos_emb[0], pos_emb[1], pos_emb[2],
            dep_emb[0], dep_emb[1], dep_emb[2],
            out);
    }
}

// round 12
// speedup vs baseline: 1.1852x; 1.0670x over previous
#include <cuda_runtime.h>
#include <cuda_fp16.h>

// Problem constants
#define S_TOTAL    37448       // sum of LAYER_SIZES
#define OUT_TOKENS 5704        // 8 + 64 + 512 + 1024 + 4096
#define BATCH      8
#define NROWS      196         // 4 val rows + 3*64 pos rows
#define PR_ROWS    4           // rows per projection block (49 chunks)

// Scratch (static device globals; no runtime allocation)
__device__ float  g_Wt3[4 * 256 * 256];          // [kk][e][o]
__device__ float  g_Wt4[8 * 256 * 256];
__device__ __half g_proj3h[4 * NROWS * 256];     // [kk][row][o] fp16 base tables
__device__ __half g_proj4h[8 * NROWS * 256];
__device__ __half g_tabA3[4 * 256 * 256];        // [kk][v*64+q0][o]
__device__ __half g_tabA4[8 * 256 * 256];

__device__ __forceinline__ __half2 u2h2(unsigned u) {
    return *reinterpret_cast<const __half2*>(&u);
}
__device__ __forceinline__ unsigned h22u(__half2 h) {
    return *reinterpret_cast<const unsigned*>(&h);
}

// ---------------------------------------------------------------------------
// Kernel 1: fused tiled transpose for BOTH conv weights.
// ---------------------------------------------------------------------------
__global__ void __launch_bounds__(256) transpose_w_all(
    const float* __restrict__ W3, const float* __restrict__ W4)
{
    __shared__ float sm[8448];

    if (blockIdx.x < 32) {
        constexpr int TO = 64, TE = 32, PAD = 65;
        int bid = blockIdx.x;
        int o0 = (bid % 4) * TO;
        int e0 = (bid / 4) * TE;
        const float4* Wv = reinterpret_cast<const float4*>(W3);

        for (int i = threadIdx.x; i < TO * TE; i += 256) {
            int o_l = i / TE, e_l = i % TE;
            float4 v = Wv[(o0 + o_l) * 256 + (e0 + e_l)];
            sm[(0 * TE + e_l) * PAD + o_l] = v.x;
            sm[(1 * TE + e_l) * PAD + o_l] = v.y;
            sm[(2 * TE + e_l) * PAD + o_l] = v.z;
            sm[(3 * TE + e_l) * PAD + o_l] = v.w;
        }
        __syncthreads();
        for (int i = threadIdx.x; i < 4 * TE * TO; i += 256) {
            int kk = i / (TE * TO);
            int rem = i % (TE * TO);
            int e_l = rem / TO, o_l = rem % TO;
            g_Wt3[kk * 65536 + (e0 + e_l) * 256 + (o0 + o_l)] =
                sm[(kk * TE + e_l) * PAD + o_l];
        }
    } else {
        constexpr int TO = 32, TE = 32, PAD = 33;
        int bid = blockIdx.x - 32;
        int o0 = (bid % 8) * TO;
        int e0 = (bid / 8) * TE;
        const float4* Wv = reinterpret_cast<const float4*>(W4);

        for (int i = threadIdx.x; i < TO * TE; i += 256) {
            int o_l = i / TE, e_l = i % TE;
            int idx = (o0 + o_l) * 256 + (e0 + e_l);
#pragma unroll
            for (int q = 0; q < 2; q++) {
                float4 v = Wv[idx * 2 + q];
                sm[((q * 4 + 0) * TE + e_l) * PAD + o_l] = v.x;
                sm[((q * 4 + 1) * TE + e_l) * PAD + o_l] = v.y;
                sm[((q * 4 + 2) * TE + e_l) * PAD + o_l] = v.z;
                sm[((q * 4 + 3) * TE + e_l) * PAD + o_l] = v.w;
            }
        }
        __syncthreads();
        for (int i = threadIdx.x; i < 8 * TE * TO; i += 256) {
            int kk = i / (TE * TO);
            int rem = i % (TE * TO);
            int e_l = rem / TO, o_l = rem % TO;
            g_Wt4[kk * 65536 + (e0 + e_l) * 256 + (o0 + o_l)] =
                sm[(kk * TE + e_l) * PAD + o_l];
        }
    }
}

// ---------------------------------------------------------------------------
// Kernel 2: fused projection for all 12 kk-slices; emits fp16 base tables.
// ---------------------------------------------------------------------------
__global__ void __launch_bounds__(256) project_all_kernel(
    const float* __restrict__ val3, const float* __restrict__ pos3,
    const float* __restrict__ val4, const float* __restrict__ pos4)
{
    int s  = blockIdx.y;
    int r0 = blockIdx.x * PR_ROWS;

    const float* Wt; __half* proj; const float* ve; const float* pe;
    if (s < 4) { Wt = g_Wt3 + s * 65536;        proj = g_proj3h + s * (NROWS * 256);
                 ve = val3; pe = pos3; }
    else       { int kk = s - 4;
                 Wt = g_Wt4 + kk * 65536;       proj = g_proj4h + kk * (NROWS * 256);
                 ve = val4; pe = pos4; }

    int o4 = threadIdx.x & 63;
    int eh = threadIdx.x >> 6;
    int ebase = eh * 64;

    __shared__ float  srow[PR_ROWS][256];
    __shared__ float4 sred[3][PR_ROWS][64];

    for (int i = threadIdx.x; i < PR_ROWS * 256; i += 256) {
        int r = i >> 8, c = i & 255;
        int rr = r0 + r;
        srow[r][c] = (rr < 4) ? ve[rr * 256 + c] : pe[(rr - 4) * 256 + c];
    }
    __syncthreads();

    float4 acc[PR_ROWS];
#pragma unroll
    for (int r = 0; r < PR_ROWS; r++) acc[r] = make_float4(0.f, 0.f, 0.f, 0.f);

    const float4* Wv = reinterpret_cast<const float4*>(Wt);
#pragma unroll 8
    for (int e = 0; e < 64; e++) {
        float4 w = Wv[(ebase + e) * 64 + o4];
#pragma unroll
        for (int r = 0; r < PR_ROWS; r++) {
            float x = srow[r][ebase + e];
            acc[r].x += x * w.x; acc[r].y += x * w.y;
            acc[r].z += x * w.z; acc[r].w += x * w.w;
        }
    }

    if (eh > 0) {
#pragma unroll
        for (int r = 0; r < PR_ROWS; r++) sred[eh - 1][r][o4] = acc[r];
    }
    __syncthreads();
    if (eh == 0) {
#pragma unroll
        for (int r = 0; r < PR_ROWS; r++) {
            float4 a = acc[r];
            float4 b0 = sred[0][r][o4], b1 = sred[1][r][o4], b2 = sred[2][r][o4];
            a.x += b0.x + b1.x + b2.x;
            a.y += b0.y + b1.y + b2.y;
            a.z += b0.z + b1.z + b2.z;
            a.w += b0.w + b1.w + b2.w;
            __half2* dst = reinterpret_cast<__half2*>(proj + (r0 + r) * 256 + o4 * 4);
            dst[0] = __floats2half2_rn(a.x, a.y);
            dst[1] = __floats2half2_rn(a.z, a.w);
        }
    }
}

// ---------------------------------------------------------------------------
// Kernel 3: build tabA = PV[v] + PP0[q0]   (warp per output row)
// ---------------------------------------------------------------------------
__global__ void __launch_bounds__(256) build_tabA_kernel() {
    int gw   = (blockIdx.x * blockDim.x + threadIdx.x) >> 5;
    int lane = threadIdx.x & 31;
    if (gw >= 12 * 256) return;
    int s   = gw >> 8;
    int row = gw & 255;
    int v   = row >> 6;
    int q0  = row & 63;

    const uint4* proj = reinterpret_cast<const uint4*>(
        (s < 4) ? g_proj3h + s * (NROWS * 256)
                : g_proj4h + (s - 4) * (NROWS * 256));
    uint4* dst = reinterpret_cast<uint4*>(
        (s < 4) ? g_tabA3 + s * (256 * 256)
                : g_tabA4 + (s - 4) * (256 * 256));

    uint4 a = proj[v * 32 + lane];
    uint4 b = proj[(4 + q0) * 32 + lane];
    uint4 r;
    r.x = h22u(__hadd2(u2h2(a.x), u2h2(b.x)));
    r.y = h22u(__hadd2(u2h2(a.y), u2h2(b.y)));
    r.z = h22u(__hadd2(u2h2(a.z), u2h2(b.z)));
    r.w = h22u(__hadd2(u2h2(a.w), u2h2(b.w)));
    dst[row * 32 + lane] = r;
}

// ---------------------------------------------------------------------------
// Kernel: layers 0-2 (pure embedding sum), fp32 exact.
// ---------------------------------------------------------------------------
__global__ void __launch_bounds__(256) embed_small_kernel(
    const int* __restrict__ value,
    const int* __restrict__ depth,
    const int* __restrict__ position,
    const float* __restrict__ v0, const float* __restrict__ v1, const float* __restrict__ v2,
    const float* __restrict__ p0, const float* __restrict__ p1, const float* __restrict__ p2,
    const float* __restrict__ d0, const float* __restrict__ d1, const float* __restrict__ d2,
    float* __restrict__ out)
{
    int idx = blockIdx.x * blockDim.x + threadIdx.x;
    int lane  = idx & 63;
    int token = idx >> 6;
    if (token >= BATCH * 584) return;
    int b = token / 584;
    int s = token % 584;

    const float *ve, *pe, *de;
    if (s < 8)       { ve = v0; pe = p0; de = d0; }
    else if (s < 72) { ve = v1; pe = p1; de = d1; }
    else             { ve = v2; pe = p2; de = d2; }

    int base = b * S_TOTAL + s;
    int v = value[base];
    int d = depth[base];
    const int* pp = position + base * 3;
    int q0 = pp[0], q1 = pp[1], q2 = pp[2];

    const float4* V  = reinterpret_cast<const float4*>(ve) + v * 64 + lane;
    const float4* P0 = reinterpret_cast<const float4*>(pe) + (q0)       * 64 + lane;
    const float4* P1 = reinterpret_cast<const float4*>(pe) + (64 + q1)  * 64 + lane;
    const float4* P2 = reinterpret_cast<const float4*>(pe) + (128 + q2) * 64 + lane;
    const float4* D  = reinterpret_cast<const float4*>(de) + d * 64 + lane;

    float4 a = *V, x;
    x = *P0; a.x += x.x; a.y += x.y; a.z += x.z; a.w += x.w;
    x = *P1; a.x += x.x; a.y += x.y; a.z += x.z; a.w += x.w;
    x = *P2; a.x += x.x; a.y += x.y; a.z += x.z; a.w += x.w;
    x = *D;  a.x += x.x; a.y += x.y; a.z += x.z; a.w += x.w;

    reinterpret_cast<float4*>(out)[(b * OUT_TOKENS + s) * 64 + lane] = a;
}

// ---------------------------------------------------------------------------
// Kernel: conv via tabA + proj gathers — 3 gathers per kk (R9 body, proven).
// warp = one token; indices fetched lane-parallel, prefused, shfl-broadcast.
// ---------------------------------------------------------------------------
template <int K>
__global__ void __launch_bounds__(256) conv_tri_kernel(
    const int* __restrict__ value,
    const int* __restrict__ position,
    const float* __restrict__ bias,
    float* __restrict__ out,
    int in_start, int out_row_start, int t_per_b)
{
    const __half* tabA = (K == 4) ? g_tabA3 : g_tabA4;
    const __half* proj = (K == 4) ? g_proj3h : g_proj4h;

    int gwarp = (blockIdx.x * blockDim.x + threadIdx.x) >> 5;
    int lane  = threadIdx.x & 31;
    if (gwarp >= BATCH * t_per_b) return;
    int b = gwarp / t_per_b;
    int t = gwarp % t_per_b;

    int sbase = b * S_TOTAL + in_start + t * K;

    int vload = (lane < K)     ? value[sbase + lane]        : 0;
    int pload = (lane < 3 * K) ? position[sbase * 3 + lane] : 0;

    int q0l = __shfl_sync(0xffffffffu, pload, (lane * 3)     & 31);
    int q1l = __shfl_sync(0xffffffffu, pload, (lane * 3 + 1) & 31);
    int q2l = __shfl_sync(0xffffffffu, pload, (lane * 3 + 2) & 31);
    int iA = vload * 64 + q0l;
    int i1 = 68 + q1l;
    int i2 = 132 + q2l;

    float acc[8];
    {
        const float4* bv = reinterpret_cast<const float4*>(bias);
        float4 b0 = bv[lane * 2], b1 = bv[lane * 2 + 1];
        acc[0] = b0.x; acc[1] = b0.y; acc[2] = b0.z; acc[3] = b0.w;
        acc[4] = b1.x; acc[5] = b1.y; acc[6] = b1.z; acc[7] = b1.w;
    }

#pragma unroll
    for (int kk = 0; kk < K; kk++) {
        int rA = __shfl_sync(0xffffffffu, iA, kk);
        int r1 = __shfl_sync(0xffffffffu, i1, kk);
        int r2 = __shfl_sync(0xffffffffu, i2, kk);

        const uint4* PA = reinterpret_cast<const uint4*>(tabA + kk * (256 * 256));
        const uint4* PP = reinterpret_cast<const uint4*>(proj + kk * (NROWS * 256));
        uint4 ua = PA[rA * 32 + lane];
        uint4 u1 = PP[r1 * 32 + lane];
        uint4 u2 = PP[r2 * 32 + lane];

        __half2 sx = __hadd2(__hadd2(u2h2(ua.x), u2h2(u1.x)), u2h2(u2.x));
        __half2 sy = __hadd2(__hadd2(u2h2(ua.y), u2h2(u1.y)), u2h2(u2.y));
        __half2 sz = __hadd2(__hadd2(u2h2(ua.z), u2h2(u1.z)), u2h2(u2.z));
        __half2 sw = __hadd2(__hadd2(u2h2(ua.w), u2h2(u1.w)), u2h2(u2.w));

        float2 f;
        f = __half22float2(sx); acc[0] += f.x; acc[1] += f.y;
        f = __half22float2(sy); acc[2] += f.x; acc[3] += f.y;
        f = __half22float2(sz); acc[4] += f.x; acc[5] += f.y;
        f = __half22float2(sw); acc[6] += f.x; acc[7] += f.y;
    }

    int row = b * OUT_TOKENS + out_row_start + t;
    float4* dst = reinterpret_cast<float4*>(out + row * 256 + lane * 8);
    dst[0] = make_float4(acc[0], acc[1], acc[2], acc[3]);
    dst[1] = make_float4(acc[4], acc[5], acc[6], acc[7]);
}

// ---------------------------------------------------------------------------
// Launch. Inputs classified BY ELEMENT COUNT.
// Two-stream fork/join (graph-capturable): s0 = transpose->project->buildA->
// conv4; s1 = embed (t=0) then conv3 after tables. Join before return.
// Submission order keeps conv4 as launch #4 (ncu capture slot).
// ---------------------------------------------------------------------------
extern "C" void kernel_launch(void* const* d_in, const int* in_sizes, int n_in,
                              void* d_out, int out_size) {
    const int* value = nullptr;
    const int* depth = nullptr;
    const int* position = nullptr;
    const float* val_emb[5] = {};
    const float* pos_emb[5] = {};
    const float* dep_emb[3] = {};
    const float* conv_w3 = nullptr;
    const float* conv_w4 = nullptr;
    const float* conv_b3 = nullptr;
    const float* conv_b4 = nullptr;

    int n_val = 0, n_pos = 0, n_dep = 0, n_cb = 0, n_vd = 0;
    for (int i = 0; i < n_in; i++) {
        int sz = in_sizes[i];
        const void* p = d_in[i];
        switch (sz) {
            case 299584:
                if (n_vd++ == 0) value = (const int*)p; else depth = (const int*)p;
                break;
            case 898752:  position = (const int*)p; break;
            case 1024:    if (n_val < 5) val_emb[n_val++] = (const float*)p; break;
            case 49152:   if (n_pos < 5) pos_emb[n_pos++] = (const float*)p; break;
            case 1536:    if (n_dep < 3) dep_emb[n_dep++] = (const float*)p; break;
            case 262144:  conv_w3 = (const float*)p; break;
            case 524288:  conv_w4 = (const float*)p; break;
            case 256:
                if (n_cb++ == 0) conv_b3 = (const float*)p; else conv_b4 = (const float*)p;
                break;
            default: break;
        }
    }

    float* out = (float*)d_out;

    // Lazily-created side stream + events (host objects only; created on the
    // pre-capture correctness call, reused under capture).
    static cudaStream_t s1 = nullptr;
    static cudaEvent_t evStart = nullptr, evTables = nullptr, evSide = nullptr;
    if (!s1) {
        cudaStreamCreateWithFlags(&s1, cudaStreamNonBlocking);
        cudaEventCreateWithFlags(&evStart,  cudaEventDisableTiming);
        cudaEventCreateWithFlags(&evTables, cudaEventDisableTiming);
        cudaEventCreateWithFlags(&evSide,   cudaEventDisableTiming);
    }

    // Fork point on the main (capture-origin) stream.
    cudaEventRecord(evStart, 0);

    // ---- main stream: precompute chain + conv4 ----
    transpose_w_all<<<96, 256>>>(conv_w3, conv_w4);                         // #1
    project_all_kernel<<<dim3(NROWS / PR_ROWS, 12), 256>>>(                 // #2
        val_emb[3], pos_emb[3], val_emb[4], pos_emb[4]);
    build_tabA_kernel<<<(12 * 256) / 8, 256>>>();                           // #3
    cudaEventRecord(evTables, 0);

    {   // #4 (ncu capture slot): conv4
        int warps4 = BATCH * 4096;
        conv_tri_kernel<8><<<(warps4 * 32 + 255) / 256, 256>>>(
            value, position, conv_b4, out,
            /*in_start=*/4680, /*out_row_start=*/1608, /*t_per_b=*/4096);
    }

    // ---- side stream: embed at t=0, conv3 after tables ----
    cudaStreamWaitEvent(s1, evStart, 0);
    {   // #5: embed layers 0-2 (independent of precompute)
        int threads = BATCH * 584 * 64;
        embed_small_kernel<<<(threads + 255) / 256, 256, 0, s1>>>(
            value, depth, position,
            val_emb[0], val_emb[1], val_emb[2],
            pos_emb[0], pos_emb[1], pos_emb[2],
            dep_emb[0], dep_emb[1], dep_emb[2],
            out);
    }
    cudaStreamWaitEvent(s1, evTables, 0);
    {   // #6: conv3, concurrent with conv4
        int warps3 = BATCH * 1024;
        conv_tri_kernel<4><<<(warps3 * 32 + 255) / 256, 256, 0, s1>>>(
            value, position, conv_b3, out,
            /*in_start=*/584, /*out_row_start=*/584, /*t_per_b=*/1024);
    }
    cudaEventRecord(evSide, s1);

    // Join: main stream (and thus the captured graph's leaf) waits for s1.
    cudaStreamWaitEvent(0, evSide, 0);
}